// round 11
// baseline (speedup 1.0000x reference)
#include <cuda_runtime.h>
#include <cuda_bf16.h>

#define KDIM 64
#define PF   4   // prefetch depth (steps)

__device__ float g_partial[1024];
__device__ int   g_done = 0;

typedef unsigned long long ull;
template <int N> struct IC { static constexpr int v = N; };

__device__ __forceinline__ void fma2(ull& acc, ull a, ull b) {
    asm("fma.rn.f32x2 %0, %1, %2, %3;" : "=l"(acc) : "l"(a), "l"(b), "l"(acc));
}
__device__ __forceinline__ void add2(ull& d, ull a, ull b) {
    asm("add.rn.f32x2 %0, %1, %2;" : "=l"(d) : "l"(a), "l"(b));
}
__device__ __forceinline__ float sum2(ull v) {
    return __uint_as_float((unsigned)v) + __uint_as_float((unsigned)(v >> 32));
}

// TWO batches per warp (batch pair (blockIdx.x, blockIdx.x + B/2)), sharing
// the E = exp(trans) register set (64 f32x2 pairs = 128 regs, paid once).
// Lane l owns columns j0=2l, j1=2l+1 of BOTH batches. The two recursions are
// independent chains: interleaving them hides the STS->LDS->FMA-tree latency
// that bound every earlier round. Linear-space recursion with exact
// power-of-2 renorm; per-dot accumulation uses 2 chains (p0,p1 / q0,q1).
__global__ __launch_bounds__(32, 1)
void crf_fused_kernel(const float* __restrict__ emis,
                      const float* __restrict__ trans,
                      const float* __restrict__ start_t,
                      const float* __restrict__ end_t,
                      const int*  __restrict__ labels,
                      const int*  __restrict__ sent_len,
                      int T, int B, float* __restrict__ out)
{
    const int lane = threadIdx.x;
    const int j0   = 2 * lane;
    const int j1   = j0 + 1;
    const int half = B >> 1;
    const int bid0 = blockIdx.x;
    const int bid1 = blockIdx.x + half;

    const float* em[2];
    const int*   lab[2];
    int L[2];
    em[0]  = emis   + (size_t)bid0 * T * KDIM;
    em[1]  = emis   + (size_t)bid1 * T * KDIM;
    lab[0] = labels + (size_t)bid0 * T;
    lab[1] = labels + (size_t)bid1 * T;
    L[0] = sent_len[bid0];
    L[1] = sent_len[bid1];

    __shared__ __align__(16) float sa[2][2][KDIM];   // [batch][buf][state]

    // shared E registers (both batches use the same transition matrix)
    ull Epk0[KDIM / 2], Epk1[KDIM / 2];
#pragma unroll
    for (int i2 = 0; i2 < KDIM / 2; ++i2) {
        const float a00 = __expf(trans[(2 * i2)     * KDIM + j0]);
        const float a10 = __expf(trans[(2 * i2 + 1) * KDIM + j0]);
        const float a01 = __expf(trans[(2 * i2)     * KDIM + j1]);
        const float a11 = __expf(trans[(2 * i2 + 1) * KDIM + j1]);
        Epk0[i2] = (ull)__float_as_uint(a00) | ((ull)__float_as_uint(a10) << 32);
        Epk1[i2] = (ull)__float_as_uint(a01) | ((ull)__float_as_uint(a11) << 32);
    }

    // per-batch state
    float ax[2], ay[2], ge[2], gt[2];
    int   Stot[2], lab_last[2], lab_roll[2];
    float2 er[2][PF];
    float  tvr[2][PF];
    int    lbr[2][PF];

    const float2 st = ((const float2*)start_t)[lane];
#pragma unroll
    for (int s = 0; s < 2; ++s) {
        const float2 e0 = ((const float2*)em[s])[lane];
        const float lx = st.x + e0.x;
        const float ly = st.y + e0.y;
        ax[s] = __expf(lx);
        ay[s] = __expf(ly);
        Stot[s] = 0; ge[s] = 0.0f; gt[s] = 0.0f;
        lab_last[s] = lab[s][0];
        if (j0 == lab_last[s]) ge[s] = lx;
        if (j1 == lab_last[s]) ge[s] = ly;
        lab_roll[s] = lab_last[s];
#pragma unroll
        for (int k = 0; k < PF; ++k) {
            int tt = 1 + k; if (tt > T - 1) tt = T - 1;
            er[s][k] = ((const float2*)(em[s] + (size_t)tt * KDIM))[lane];
            const int l1 = lab[s][tt];
            lbr[s][k] = l1;
            tvr[s][k] = trans[lab_roll[s] * KDIM + l1];
            lab_roll[s] = l1;
        }
    }

    int buf = 0;
    const int Lmin = (L[0] < L[1]) ? L[0] : L[1];

    // ---------------- fused main loop: both batches per step ----------------
    int t = 1;
    for (; t + PF <= Lmin; t += PF) {
#pragma unroll
        for (int k = 0; k < PF; ++k) {
            float2 ec[2]; float tc[2]; int lc[2];
            // refill both rings (raw loads only)
#pragma unroll
            for (int s = 0; s < 2; ++s) {
                ec[s] = er[s][k]; tc[s] = tvr[s][k]; lc[s] = lbr[s][k];
                int tp = t + PF + k; if (tp > T - 1) tp = T - 1;
                er[s][k] = ((const float2*)(em[s] + (size_t)tp * KDIM))[lane];
                const int l1 = lab[s][tp];
                lbr[s][k] = l1;
                tvr[s][k] = trans[lab_roll[s] * KDIM + l1];
                lab_roll[s] = l1;
            }
            // PHASE A: consume-time exps + STS (both batches)
            float Px[2], Py[2];
#pragma unroll
            for (int s = 0; s < 2; ++s) {
                Px[s] = __expf(ec[s].x);
                Py[s] = __expf(ec[s].y);
                ((float2*)sa[s][buf])[lane] = make_float2(ax[s], ay[s]);
            }
            asm volatile("" ::: "memory");
            // PHASE B: gold + pivots + q=0 FMAs
            const ulonglong2* sv0 = (const ulonglong2*)sa[0][buf];
            const ulonglong2* sv1 = (const ulonglong2*)sa[1][buf];
            ull p0[2], p1[2], q0[2], q1[2];
            float scl[2];
            {
                ulonglong2 v00[2], v01[2];
                v00[0] = sv0[0]; v01[0] = sv0[1];
                v00[1] = sv1[0]; v01[1] = sv1[1];
#pragma unroll
                for (int s = 0; s < 2; ++s) {
                    if (j0 == lc[s]) ge[s] += ec[s].x;
                    if (j1 == lc[s]) ge[s] += ec[s].y;
                    gt[s] += tc[s];
                    lab_last[s] = lc[s];
                    const unsigned pb = (unsigned)v00[s].x;          // sa[s][buf][0]
                    const int e = (int)((pb >> 23) & 0xffu);
                    scl[s] = __uint_as_float((unsigned)(254 - e) << 23);
                    Stot[s] += e - 127;
                    p0[s] = p1[s] = q0[s] = q1[s] = 0ull;
                    fma2(p0[s], v00[s].x, Epk0[0]);  fma2(q0[s], v00[s].x, Epk1[0]);
                    fma2(p1[s], v00[s].y, Epk0[1]);  fma2(q1[s], v00[s].y, Epk1[1]);
                    fma2(p0[s], v01[s].x, Epk0[2]);  fma2(q0[s], v01[s].x, Epk1[2]);
                    fma2(p1[s], v01[s].y, Epk0[3]);  fma2(q1[s], v01[s].y, Epk1[3]);
                }
            }
            // PHASE C: q = 1..7, both batches interleaved
#pragma unroll
            for (int q = 1; q < 8; ++q) {
                ulonglong2 w0[2], w1[2];
                w0[0] = sv0[2 * q]; w1[0] = sv0[2 * q + 1];
                w0[1] = sv1[2 * q]; w1[1] = sv1[2 * q + 1];
#pragma unroll
                for (int s = 0; s < 2; ++s) {
                    fma2(p0[s], w0[s].x, Epk0[4 * q + 0]);  fma2(q0[s], w0[s].x, Epk1[4 * q + 0]);
                    fma2(p1[s], w0[s].y, Epk0[4 * q + 1]);  fma2(q1[s], w0[s].y, Epk1[4 * q + 1]);
                    fma2(p0[s], w1[s].x, Epk0[4 * q + 2]);  fma2(q0[s], w1[s].x, Epk1[4 * q + 2]);
                    fma2(p1[s], w1[s].y, Epk0[4 * q + 3]);  fma2(q1[s], w1[s].y, Epk1[4 * q + 3]);
                }
            }
            // PHASE D: trees + alpha updates
#pragma unroll
            for (int s = 0; s < 2; ++s) {
                add2(p0[s], p0[s], p1[s]);
                add2(q0[s], q0[s], q1[s]);
                ax[s] = sum2(p0[s]) * scl[s] * Px[s];
                ay[s] = sum2(q0[s]) * scl[s] * Py[s];
            }
            buf ^= 1;
        }
    }

    // ---------------- solo loops: finish each batch independently ----------------
    auto runSolo = [&](auto S) {
        constexpr int s = decltype(S)::v;
        int sbuf = buf;
        auto soloStep = [&](float2 s_ec, int s_lc, float s_tc) {
            const float Px = __expf(s_ec.x);
            const float Py = __expf(s_ec.y);
            ((float2*)sa[s][sbuf])[lane] = make_float2(ax[s], ay[s]);
            asm volatile("" ::: "memory");
            if (j0 == s_lc) ge[s] += s_ec.x;
            if (j1 == s_lc) ge[s] += s_ec.y;
            gt[s] += s_tc;
            lab_last[s] = s_lc;
            const ulonglong2* sv = (const ulonglong2*)sa[s][sbuf];
            const ulonglong2 v00 = sv[0];
            const ulonglong2 v01 = sv[1];
            const unsigned pb = (unsigned)v00.x;
            const int e = (int)((pb >> 23) & 0xffu);
            const float scl = __uint_as_float((unsigned)(254 - e) << 23);
            Stot[s] += e - 127;
            ull a0 = 0ull, a1 = 0ull, c0 = 0ull, c1 = 0ull;
            fma2(a0, v00.x, Epk0[0]);  fma2(c0, v00.x, Epk1[0]);
            fma2(a1, v00.y, Epk0[1]);  fma2(c1, v00.y, Epk1[1]);
            fma2(a0, v01.x, Epk0[2]);  fma2(c0, v01.x, Epk1[2]);
            fma2(a1, v01.y, Epk0[3]);  fma2(c1, v01.y, Epk1[3]);
#pragma unroll
            for (int q = 1; q < 8; ++q) {
                const ulonglong2 w0 = sv[2 * q];
                const ulonglong2 w1 = sv[2 * q + 1];
                fma2(a0, w0.x, Epk0[4 * q + 0]);  fma2(c0, w0.x, Epk1[4 * q + 0]);
                fma2(a1, w0.y, Epk0[4 * q + 1]);  fma2(c1, w0.y, Epk1[4 * q + 1]);
                fma2(a0, w1.x, Epk0[4 * q + 2]);  fma2(c0, w1.x, Epk1[4 * q + 2]);
                fma2(a1, w1.y, Epk0[4 * q + 3]);  fma2(c1, w1.y, Epk1[4 * q + 3]);
            }
            add2(a0, a0, a1);
            add2(c0, c0, c1);
            ax[s] = sum2(a0) * scl * Px;
            ay[s] = sum2(c0) * scl * Py;
            sbuf ^= 1;
        };
        int ts = t;
        for (; ts + PF <= L[s]; ts += PF) {
#pragma unroll
            for (int k = 0; k < PF; ++k) {
                const float2 ec2 = er[s][k];
                const float  tc2 = tvr[s][k];
                const int    lc2 = lbr[s][k];
                int tp = ts + PF + k; if (tp > T - 1) tp = T - 1;
                er[s][k] = ((const float2*)(em[s] + (size_t)tp * KDIM))[lane];
                const int l1 = lab[s][tp];
                lbr[s][k] = l1;
                tvr[s][k] = trans[lab_roll[s] * KDIM + l1];
                lab_roll[s] = l1;
                soloStep(ec2, lc2, tc2);
            }
        }
        for (int k = 0; ts < L[s]; ++ts, ++k)
            soloStep(er[s][k], lbr[s][k], tvr[s][k]);
    };
    runSolo(IC<0>{});
    runSolo(IC<1>{});

    // ---------------- finalize both batches ----------------
    const float2 en = ((const float2*)end_t)[lane];
    const float enx = __expf(en.x);
    const float eny = __expf(en.y);
#pragma unroll
    for (int s = 0; s < 2; ++s) {
        float geF = ge[s];
        if (j0 == lab_last[s]) geF += en.x;
        if (j1 == lab_last[s]) geF += en.y;
        float xs = ax[s] * enx + ay[s] * eny;
        float gg = geF;
#pragma unroll
        for (int o = 16; o; o >>= 1) {
            xs += __shfl_xor_sync(0xffffffffu, xs, o);
            gg += __shfl_xor_sync(0xffffffffu, gg, o);
        }
        if (lane == 0) {
            const float fwd = __logf(xs) + (float)Stot[s] * 0.69314718055994530942f;
            g_partial[(s == 0) ? bid0 : bid1] = fwd - (gg + gt[s]);
        }
    }

    // ---------------- finisher: last block reduces all partials ----------------
    __threadfence();
    int isLast = 0;
    if (lane == 0) {
        const int old = atomicAdd(&g_done, 1);
        isLast = (old == half - 1);
    }
    isLast = __shfl_sync(0xffffffffu, isLast, 0);
    if (isLast) {
        __threadfence();
        float v = 0.0f;
        for (int i = lane; i < B; i += 32) v += g_partial[i];
#pragma unroll
        for (int o = 16; o; o >>= 1) v += __shfl_xor_sync(0xffffffffu, v, o);
        if (lane == 0) {
            out[0] = v / (float)B;
            g_done = 0;
        }
    }
}

extern "C" void kernel_launch(void* const* d_in, const int* in_sizes, int n_in,
                              void* d_out, int out_size)
{
    const float* emis    = (const float*)d_in[0];
    const float* trans   = (const float*)d_in[1];
    const float* start_t = (const float*)d_in[2];
    const float* end_t   = (const float*)d_in[3];
    const int*   labels  = (const int*)d_in[4];
    const int*   slen    = (const int*)d_in[5];

    const int B = in_sizes[5];            // 512
    const int T = in_sizes[4] / B;        // 1024
    float* out = (float*)d_out;

    crf_fused_kernel<<<B / 2, 32>>>(emis, trans, start_t, end_t, labels, slen, T, B, out);
}